// round 15
// baseline (speedup 1.0000x reference)
#include <cuda_runtime.h>
#include <cuda_bf16.h>
#include <cstdint>

#define VOCAB   1000000
#define EMB     50
#define OUTD    2
#define BATCH   128
#define SEQ     2000

#define NWARPS  32                  // 1024 threads per block
#define NTHREADS (NWARPS * 32)
#define ROWBYTES 200                // 50 * 4

// ---------------------------------------------------------------------------
// One block per batch row (proven best shape). Hot-loop slimmed:
//   - packed f32x2 accumulate (1 instr instead of 2 FADD)
//   - single sign-check predicate per token
//   - one IMAD.WIDE per token for addressing (per-lane byte base precomputed)
// ---------------------------------------------------------------------------
__global__ __launch_bounds__(NTHREADS)
void fused_rowpool_kernel(const int* __restrict__ t,
                          const float* __restrict__ emb,
                          const float* __restrict__ W,
                          const float* __restrict__ bias,
                          float* __restrict__ out)
{
    const int b    = blockIdx.x;
    const int tid  = threadIdx.x;
    const int wid  = tid >> 5;
    const int lane = tid & 31;

    __shared__ int                sidx[SEQ];          // 8 KB
    __shared__ unsigned long long sred[NWARPS][25];   // 6.4 KB

    // Stage this row's 2000 indices (coalesced, 2 per thread).
    const int* tp = t + (size_t)b * SEQ;
    #pragma unroll
    for (int i = tid; i < SEQ; i += NTHREADS) {
        sidx[i] = tp[i];
    }
    __syncthreads();

    // Per-lane byte base: lane L owns floats {2L, 2L+1} of every row.
    const char* embB = (const char*)emb + (size_t)lane * 8;

    unsigned long long acc = 0;   // packed (f32 lo, f32 hi) = (0.0f, 0.0f)
    if (lane < 25) {
        #pragma unroll 8
        for (int i = wid; i < SEQ; i += NWARPS) {
            int idx = sidx[i];
            if (idx >= 0) {
                unsigned long long v =
                    __ldg((const unsigned long long*)(embB + (size_t)idx * ROWBYTES));
                asm("add.rn.f32x2 %0, %0, %1;" : "+l"(acc) : "l"(v));
            }
        }
        sred[wid][lane] = acc;
    }
    __syncthreads();

    // Warp 0: reduce the 32 warp partials (packed), project onto W, finish.
    if (tid < 32) {
        float d0 = 0.0f, d1 = 0.0f;
        if (tid < 25) {
            unsigned long long p = 0;
            #pragma unroll
            for (int w = 0; w < NWARPS; w++) {
                asm("add.rn.f32x2 %0, %0, %1;" : "+l"(p) : "l"(sred[w][tid]));
            }
            float px, py;
            asm("mov.b64 {%0, %1}, %2;" : "=f"(px), "=f"(py) : "l"(p));
            d0 = px * W[2 * tid]       + py * W[2 * tid + 1];       // W row 0
            d1 = px * W[EMB + 2 * tid] + py * W[EMB + 2 * tid + 1]; // W row 1
        }
        #pragma unroll
        for (int off = 16; off > 0; off >>= 1) {
            d0 += __shfl_down_sync(0xFFFFFFFFu, d0, off);
            d1 += __shfl_down_sync(0xFFFFFFFFu, d1, off);
        }
        if (tid == 0) {
            const float inv = 1.0f / (float)BATCH;
            out[b * OUTD + 0] = fmaxf(d0 * inv + bias[0], 0.0f);
            out[b * OUTD + 1] = fmaxf(d1 * inv + bias[1], 0.0f);
        }
    }
}

// ---------------------------------------------------------------------------
// Inputs: t [128,2000] int32, embeddings [1e6,50] f32, W [2,50] f32, b [2] f32.
// Output: [128,2] f32.
// ---------------------------------------------------------------------------
extern "C" void kernel_launch(void* const* d_in, const int* in_sizes, int n_in,
                              void* d_out, int out_size)
{
    const int*   t   = (const int*)d_in[0];
    const float* emb = (const float*)d_in[1];
    const float* W   = (const float*)d_in[2];
    const float* bia = (const float*)d_in[3];
    float*       out = (float*)d_out;

    fused_rowpool_kernel<<<BATCH, NTHREADS>>>(t, emb, W, bia, out);
}